// round 1
// baseline (speedup 1.0000x reference)
#include <cuda_runtime.h>
#include <math.h>
#include <stdint.h>

#define B_ 2
#define S_ 2048
#define D_ 1024
#define H_ 16
#define KH_ 4
#define HD_ 64
#define E_ 8
#define FF_ 2048
#define NTOK (B_*S_)            // 4096
#define NSLOT (NTOK*2)          // 8192 (token, expert) pairs
#define NEG_BIG -3.0e38f

// ---------------- scratch (device globals: allocation-free) ----------------
__device__ float g_xn  [NTOK*D_];
__device__ float g_q   [NTOK*H_*HD_];
__device__ float g_k   [NTOK*KH_*HD_];
__device__ float g_v   [NTOK*KH_*HD_];
__device__ float g_gate[NTOK*H_*HD_];
__device__ float g_attn[NTOK*H_*HD_];
__device__ float g_x1  [NTOK*D_];
__device__ float g_xn2 [NTOK*D_];
__device__ float g_h   [NSLOT*FF_];   // h1 then h (in place)
__device__ float g_tmp [NSLOT*D_];    // per-slot expert outputs (scaled)
__device__ int   g_topi[NTOK*2];
__device__ float g_topv[NTOK*2];
__device__ int   g_permTok[NSLOT];
__device__ float g_permW  [NSLOT];
__device__ int   g_tokSlot[NTOK*2];
__device__ int   g_counts[E_];
__device__ int   g_off   [E_+1];
__device__ int   g_cursor[E_];
__device__ float g_probsum[E_];

// ---------------- rmsnorm over D=1024 (1 block / token, 256 thr) ----------
__global__ void rmsnorm_kernel(const float* __restrict__ x,
                               const float* __restrict__ w,
                               float* __restrict__ out, float eps) {
    int t = blockIdx.x;
    const float4* xr = (const float4*)(x + (size_t)t * D_);
    float4 v = xr[threadIdx.x];
    float ss = v.x*v.x + v.y*v.y + v.z*v.z + v.w*v.w;
    __shared__ float sm[8];
    for (int o = 16; o > 0; o >>= 1) ss += __shfl_xor_sync(0xffffffffu, ss, o);
    if ((threadIdx.x & 31) == 0) sm[threadIdx.x >> 5] = ss;
    __syncthreads();
    if (threadIdx.x < 8) {
        float s2 = sm[threadIdx.x];
        for (int o = 4; o > 0; o >>= 1) s2 += __shfl_xor_sync(0xffu, s2, o);
        if (threadIdx.x == 0) sm[0] = s2;
    }
    __syncthreads();
    float sc = rsqrtf(sm[0] * (1.0f / D_) + eps);
    const float4* wr = (const float4*)w;
    float4 wv = wr[threadIdx.x];
    float4 o4 = make_float4(v.x*sc*wv.x, v.y*sc*wv.y, v.z*sc*wv.z, v.w*sc*wv.w);
    ((float4*)(out + (size_t)t * D_))[threadIdx.x] = o4;
}

// ---------------- generic SGEMM 128x128x8, 256 thr, 8x8/thread ------------
// EPI: 0 = C=acc ; 1 = C=X+acc (residual) ; 2 = C=silu(Cprev)*acc (in-place) ;
//      3 = C=X[row]*acc (per-row scale)
// rowmap: A-row gather (nullptr = identity). range: {start,end} device ptr.
template<int EPI>
__global__ void sgemm_kernel(const float* __restrict__ A, const float* __restrict__ B,
                             float* __restrict__ C, const float* __restrict__ X,
                             int M, int N, int K,
                             const int* __restrict__ rowmap,
                             const int* __restrict__ range) {
    __shared__ float As[8][128];
    __shared__ float Bs[8][128];
    int tid = threadIdx.x;
    int start = 0, end = M;
    if (range) { start = range[0]; end = range[1]; }
    int rowbase = start + blockIdx.y * 128;
    if (rowbase >= end) return;
    int nbase = blockIdx.x * 128;
    int tx = tid & 15, ty = tid >> 4;
    int arow_l = tid >> 1;
    int acol_l = (tid & 1) * 4;
    int brow_l = tid >> 5;
    int bcol_l = (tid & 31) * 4;
    int grow_l = rowbase + arow_l;
    bool avalid = grow_l < end;
    int arow_g = 0;
    if (avalid) arow_g = rowmap ? rowmap[grow_l] : grow_l;
    const float* Aptr = A + (size_t)arow_g * K + acol_l;
    const float* Bptr = B + (size_t)brow_l * N + nbase + bcol_l;

    float acc[8][8];
#pragma unroll
    for (int i = 0; i < 8; i++)
#pragma unroll
        for (int j = 0; j < 8; j++) acc[i][j] = 0.f;

    for (int k0 = 0; k0 < K; k0 += 8) {
        float4 a4 = avalid ? *(const float4*)(Aptr + k0) : make_float4(0, 0, 0, 0);
        As[acol_l + 0][arow_l] = a4.x;
        As[acol_l + 1][arow_l] = a4.y;
        As[acol_l + 2][arow_l] = a4.z;
        As[acol_l + 3][arow_l] = a4.w;
        float4 b4 = *(const float4*)(Bptr + (size_t)k0 * N);
        *(float4*)&Bs[brow_l][bcol_l] = b4;
        __syncthreads();
#pragma unroll
        for (int kk = 0; kk < 8; kk++) {
            float ar[8], br[8];
#pragma unroll
            for (int i = 0; i < 8; i++) ar[i] = As[kk][ty * 8 + i];
#pragma unroll
            for (int j = 0; j < 8; j++) br[j] = Bs[kk][tx * 8 + j];
#pragma unroll
            for (int i = 0; i < 8; i++)
#pragma unroll
                for (int j = 0; j < 8; j++) acc[i][j] += ar[i] * br[j];
        }
        __syncthreads();
    }
#pragma unroll
    for (int i = 0; i < 8; i++) {
        int grow = rowbase + ty * 8 + i;
        if (grow >= end) continue;
        size_t rowoff = (size_t)grow * N;
#pragma unroll
        for (int j = 0; j < 8; j++) {
            int col = nbase + tx * 8 + j;
            size_t idx = rowoff + col;
            float v = acc[i][j];
            if (EPI == 0) {
                C[idx] = v;
            } else if (EPI == 1) {
                C[idx] = X[idx] + v;
            } else if (EPI == 2) {
                float h1 = C[idx];
                C[idx] = h1 / (1.f + __expf(-h1)) * v;
            } else {
                C[idx] = X[grow] * v;
            }
        }
    }
}

// -------- per-head rmsnorm (eps 1e-5) + RoPE, one warp per (token, head) ---
__global__ void qkrope_kernel(float* buf, const float* __restrict__ w,
                              int nheads, int ntok) {
    int wid = (blockIdx.x * blockDim.x + threadIdx.x) >> 5;
    int lane = threadIdx.x & 31;
    if (wid >= ntok * nheads) return;
    int t = wid / nheads, h = wid - t * nheads;
    int pos = t & (S_ - 1);
    size_t base = (size_t)t * nheads * HD_ + h * HD_;
    float v0 = buf[base + 2 * lane];
    float v1 = buf[base + 2 * lane + 1];
    float ss = v0 * v0 + v1 * v1;
    for (int o = 16; o > 0; o >>= 1) ss += __shfl_xor_sync(0xffffffffu, ss, o);
    float sc = rsqrtf(ss * (1.0f / HD_) + 1e-5f);
    float a  = v0 * sc * w[2 * lane];
    float b2 = v1 * sc * w[2 * lane + 1];
    // inv = 10000^(-2*lane/64)
    float inv = expf(-(float)lane * (2.0f / HD_) * 9.210340371976184f);
    float ang = (float)pos * inv;
    float cs = cosf(ang), sn = sinf(ang);
    buf[base + 2 * lane]     = a * cs - b2 * sn;
    buf[base + 2 * lane + 1] = a * sn + b2 * cs;
}

// ---------------- flash attention, causal, BQ=64 BK=32, 256 thr ------------
__global__ void attn_kernel(const float* __restrict__ Q, const float* __restrict__ Kb,
                            const float* __restrict__ Vb, float* __restrict__ O) {
    __shared__ float Qs[64][68];
    __shared__ float Ks[32][68];
    __shared__ float Vs[32][68];
    __shared__ float Ps[64][36];
    int qt = blockIdx.x, h = blockIdx.y, b = blockIdx.z;
    int kh = h >> 2;
    int tid = threadIdx.x;
    int r = tid >> 2, c = tid & 3;   // row 0..63, quad 0..3

    {   // load + scale Q tile
        int row = tid >> 2;
        int col0 = (tid & 3) * 16;
        size_t base = ((size_t)(b * S_ + qt * 64 + row)) * (H_ * HD_) + h * HD_ + col0;
#pragma unroll
        for (int i = 0; i < 4; i++) {
            float4 v = *(const float4*)(Q + base + i * 4);
            Qs[row][col0 + i * 4 + 0] = v.x * 0.125f;
            Qs[row][col0 + i * 4 + 1] = v.y * 0.125f;
            Qs[row][col0 + i * 4 + 2] = v.z * 0.125f;
            Qs[row][col0 + i * 4 + 3] = v.w * 0.125f;
        }
    }

    float o[16];
#pragma unroll
    for (int i = 0; i < 16; i++) o[i] = 0.f;
    float m = NEG_BIG, l = 0.f;
    int qg = qt * 64 + r;
    int nkt = 2 * (qt + 1);

    for (int kt = 0; kt < nkt; kt++) {
        __syncthreads();  // previous-iter smem reads done (also covers Qs fill)
        {   // load K,V tile: 32 rows x 64
            int row = tid >> 3;
            int col0 = (tid & 7) * 8;
            size_t base = ((size_t)(b * S_ + kt * 32 + row)) * (KH_ * HD_) + kh * HD_ + col0;
            float4 k1 = *(const float4*)(Kb + base);
            float4 k2 = *(const float4*)(Kb + base + 4);
            *(float4*)&Ks[row][col0]     = k1;
            *(float4*)&Ks[row][col0 + 4] = k2;
            float4 v1 = *(const float4*)(Vb + base);
            float4 v2 = *(const float4*)(Vb + base + 4);
            *(float4*)&Vs[row][col0]     = v1;
            *(float4*)&Vs[row][col0 + 4] = v2;
        }
        __syncthreads();

        float p[8];
        float tmax = NEG_BIG;
#pragma unroll
        for (int jj = 0; jj < 8; jj++) {
            int j = c * 8 + jj;
            float s = 0.f;
#pragma unroll
            for (int d = 0; d < 64; d++) s += Qs[r][d] * Ks[j][d];
            int kg = kt * 32 + j;
            if (kg > qg) s = NEG_BIG;
            p[jj] = s;
            tmax = fmaxf(tmax, s);
        }
        tmax = fmaxf(tmax, __shfl_xor_sync(0xffffffffu, tmax, 1));
        tmax = fmaxf(tmax, __shfl_xor_sync(0xffffffffu, tmax, 2));
        float m_new = fmaxf(m, tmax);
        float alpha = __expf(m - m_new);  // underflows to 0 on first tile
        float ls = 0.f;
#pragma unroll
        for (int jj = 0; jj < 8; jj++) {
            float e = __expf(p[jj] - m_new);
            p[jj] = e;
            ls += e;
        }
        ls += __shfl_xor_sync(0xffffffffu, ls, 1);
        ls += __shfl_xor_sync(0xffffffffu, ls, 2);
        l = l * alpha + ls;
        m = m_new;
#pragma unroll
        for (int dd = 0; dd < 16; dd++) o[dd] *= alpha;
#pragma unroll
        for (int jj = 0; jj < 8; jj++) Ps[r][c * 8 + jj] = p[jj];
        __syncthreads();
#pragma unroll
        for (int j2 = 0; j2 < 32; j2++) {
            float pv = Ps[r][j2];
#pragma unroll
            for (int dd = 0; dd < 16; dd++) o[dd] += pv * Vs[j2][c * 16 + dd];
        }
    }
    float inv_l = 1.f / l;
    size_t obase = ((size_t)(b * S_ + qg)) * (H_ * HD_) + h * HD_ + c * 16;
#pragma unroll
    for (int dd = 0; dd < 16; dd++) O[obase + dd] = o[dd] * inv_l;
}

// ---------------- elementwise: gate = attn * sigmoid(gate) -----------------
__global__ void gatemul_kernel() {
    size_t i = (size_t)blockIdx.x * 256 + threadIdx.x;
    float g = g_gate[i];
    g_gate[i] = g_attn[i] * (1.f / (1.f + expf(-g)));
}

// ---------------- router: logits, softmax, top2, aux partials --------------
__global__ void router_kernel(const float* __restrict__ rw) {
    int t = blockIdx.x;
    const float* x = g_xn2 + (size_t)t * D_;
    float le[8] = {0, 0, 0, 0, 0, 0, 0, 0};
    for (int d = threadIdx.x; d < D_; d += 256) {
        float xv = x[d];
        const float4* r4 = (const float4*)(rw + (size_t)d * 8);
        float4 aa = r4[0], bb = r4[1];
        le[0] += xv * aa.x; le[1] += xv * aa.y; le[2] += xv * aa.z; le[3] += xv * aa.w;
        le[4] += xv * bb.x; le[5] += xv * bb.y; le[6] += xv * bb.z; le[7] += xv * bb.w;
    }
#pragma unroll
    for (int e = 0; e < 8; e++)
        for (int o = 16; o > 0; o >>= 1)
            le[e] += __shfl_xor_sync(0xffffffffu, le[e], o);
    __shared__ float sm[8][8];
    if ((threadIdx.x & 31) == 0)
#pragma unroll
        for (int e = 0; e < 8; e++) sm[threadIdx.x >> 5][e] = le[e];
    __syncthreads();
    if (threadIdx.x == 0) {
        float lg[8];
#pragma unroll
        for (int e = 0; e < 8; e++) {
            float s = 0.f;
            for (int w = 0; w < 8; w++) s += sm[w][e];
            lg[e] = s;
        }
        float mx = lg[0];
        for (int e = 1; e < 8; e++) mx = fmaxf(mx, lg[e]);
        float p[8], s = 0.f;
        for (int e = 0; e < 8; e++) { p[e] = expf(lg[e] - mx); s += p[e]; }
        float invs = 1.f / s;
        for (int e = 0; e < 8; e++) {
            p[e] *= invs;
            atomicAdd(&g_probsum[e], p[e]);
        }
        int i0 = 0;
        for (int e = 1; e < 8; e++) if (p[e] > p[i0]) i0 = e;
        int i1 = (i0 == 0) ? 1 : 0;
        for (int e = 0; e < 8; e++) if (e != i0 && p[e] > p[i1]) i1 = e;
        float tv0 = p[i0], tv1 = p[i1], s2 = tv0 + tv1;
        g_topi[t * 2] = i0; g_topi[t * 2 + 1] = i1;
        g_topv[t * 2] = tv0 / s2; g_topv[t * 2 + 1] = tv1 / s2;
        atomicAdd(&g_counts[i0], 1);
        atomicAdd(&g_counts[i1], 1);
    }
}

__global__ void zero_kernel() {
    int t = threadIdx.x;
    if (t < E_) { g_counts[t] = 0; g_cursor[t] = 0; g_probsum[t] = 0.f; }
}

__global__ void offsets_aux_kernel(float* __restrict__ aux_out) {
    if (threadIdx.x == 0) {
        int o = 0;
        for (int e = 0; e < E_; e++) { g_off[e] = o; o += g_counts[e]; }
        g_off[E_] = o;
        float aux = 0.f;
        for (int e = 0; e < E_; e++)
            aux += ((float)g_counts[e] / (NTOK * 2.0f)) * (g_probsum[e] / (float)NTOK);
        aux_out[0] = 0.01f * (float)E_ * aux;
    }
}

__global__ void scatter_kernel() {
    int t = blockIdx.x * 256 + threadIdx.x;
    if (t >= NTOK) return;
#pragma unroll
    for (int k2 = 0; k2 < 2; k2++) {
        int e = g_topi[t * 2 + k2];
        int pos = g_off[e] + atomicAdd(&g_cursor[e], 1);
        g_permTok[pos] = t;
        g_permW[pos] = g_topv[t * 2 + k2];
        g_tokSlot[t * 2 + k2] = pos;
    }
}

__global__ void finaladd_kernel(float* __restrict__ out) {
    size_t i = (size_t)blockIdx.x * 256 + threadIdx.x;
    int t = (int)(i >> 10);
    int d = (int)(i & 1023);
    int s0 = g_tokSlot[t * 2], s1 = g_tokSlot[t * 2 + 1];
    out[i] = g_x1[i] + g_tmp[(size_t)s0 * D_ + d] + g_tmp[(size_t)s1 * D_ + d];
}

// ---------------- host launcher -------------------------------------------
extern "C" void kernel_launch(void* const* d_in, const int* in_sizes, int n_in,
                              void* d_out, int out_size) {
    const float* x        = (const float*)d_in[0];
    const float* attn_nw  = (const float*)d_in[1];
    const float* ffn_nw   = (const float*)d_in[2];
    const float* q_nw     = (const float*)d_in[3];
    const float* k_nw     = (const float*)d_in[4];
    const float* wq       = (const float*)d_in[5];
    const float* wk       = (const float*)d_in[6];
    const float* wv       = (const float*)d_in[7];
    const float* wo       = (const float*)d_in[8];
    const float* wg       = (const float*)d_in[9];
    const float* router_w = (const float*)d_in[10];
    const float* w1       = (const float*)d_in[11];
    const float* w3       = (const float*)d_in[12];
    const float* w2       = (const float*)d_in[13];
    float* out = (float*)d_out;

    float *p_xn, *p_q, *p_k, *p_v, *p_gate, *p_attn, *p_x1, *p_xn2, *p_h, *p_tmp, *p_permW;
    int *p_permTok, *p_off;
    cudaGetSymbolAddress((void**)&p_xn, g_xn);
    cudaGetSymbolAddress((void**)&p_q, g_q);
    cudaGetSymbolAddress((void**)&p_k, g_k);
    cudaGetSymbolAddress((void**)&p_v, g_v);
    cudaGetSymbolAddress((void**)&p_gate, g_gate);
    cudaGetSymbolAddress((void**)&p_attn, g_attn);
    cudaGetSymbolAddress((void**)&p_x1, g_x1);
    cudaGetSymbolAddress((void**)&p_xn2, g_xn2);
    cudaGetSymbolAddress((void**)&p_h, g_h);
    cudaGetSymbolAddress((void**)&p_tmp, g_tmp);
    cudaGetSymbolAddress((void**)&p_permW, g_permW);
    cudaGetSymbolAddress((void**)&p_permTok, g_permTok);
    cudaGetSymbolAddress((void**)&p_off, g_off);

    // 1. attn rmsnorm
    rmsnorm_kernel<<<NTOK, 256>>>(x, attn_nw, p_xn, 1e-6f);
    // 2. QKV + gate projections
    sgemm_kernel<0><<<dim3(8, 32), 256>>>(p_xn, wq, p_q, nullptr, NTOK, 1024, 1024, nullptr, nullptr);
    sgemm_kernel<0><<<dim3(2, 32), 256>>>(p_xn, wk, p_k, nullptr, NTOK, 256, 1024, nullptr, nullptr);
    sgemm_kernel<0><<<dim3(2, 32), 256>>>(p_xn, wv, p_v, nullptr, NTOK, 256, 1024, nullptr, nullptr);
    sgemm_kernel<0><<<dim3(8, 32), 256>>>(p_xn, wg, p_gate, nullptr, NTOK, 1024, 1024, nullptr, nullptr);
    // 3. q/k norm + rope
    qkrope_kernel<<<(NTOK * H_ * 32) / 256, 256>>>(p_q, q_nw, H_, NTOK);
    qkrope_kernel<<<(NTOK * KH_ * 32) / 256, 256>>>(p_k, k_nw, KH_, NTOK);
    // 4. attention
    attn_kernel<<<dim3(S_ / 64, H_, B_), 256>>>(p_q, p_k, p_v, p_attn);
    // 5. gate
    gatemul_kernel<<<(NTOK * 1024) / 256, 256>>>();
    // 6. output proj + residual
    sgemm_kernel<1><<<dim3(8, 32), 256>>>(p_gate, wo, p_x1, x, NTOK, 1024, 1024, nullptr, nullptr);
    // 7. ffn rmsnorm
    rmsnorm_kernel<<<NTOK, 256>>>(p_x1, ffn_nw, p_xn2, 1e-6f);
    // 8. router + permutation + aux
    zero_kernel<<<1, 32>>>();
    router_kernel<<<NTOK, 256>>>(router_w);
    offsets_aux_kernel<<<1, 32>>>(out + (size_t)NTOK * D_);
    scatter_kernel<<<NTOK / 256, 256>>>();
    // 9. MoE grouped GEMMs (per-expert launches, device-side row ranges)
    for (int e = 0; e < E_; e++)
        sgemm_kernel<0><<<dim3(FF_ / 128, NSLOT / 128), 256>>>(
            p_xn2, w1 + (size_t)e * D_ * FF_, p_h, nullptr, NSLOT, FF_, D_, p_permTok, p_off + e);
    for (int e = 0; e < E_; e++)
        sgemm_kernel<2><<<dim3(FF_ / 128, NSLOT / 128), 256>>>(
            p_xn2, w3 + (size_t)e * D_ * FF_, p_h, nullptr, NSLOT, FF_, D_, p_permTok, p_off + e);
    for (int e = 0; e < E_; e++)
        sgemm_kernel<3><<<dim3(D_ / 128, NSLOT / 128), 256>>>(
            p_h, w2 + (size_t)e * FF_ * D_, p_tmp, p_permW, NSLOT, D_, FF_, nullptr, p_off + e);
    // 10. final residual add
    finaladd_kernel<<<(NTOK * 1024) / 256, 256>>>(out);
}